// round 1
// baseline (speedup 1.0000x reference)
#include <cuda_runtime.h>
#include <math.h>

// Problem constants (fixed by the dataset)
#define BB   4
#define CC   32
#define NN   2048
#define PP   12
#define OUTC 32
#define TM   128
#define TN   256     // 8 aggregated feature maps * 32 channels
#define KT   32
#define EPSV 1e-5f
#define NEG_SLOPE 0.01f

// Scratch (device globals; no runtime allocation)
__device__ float g_xp[(size_t)BB * PP * NN * CC];   // [bp][n][c], 12.6 MB
__device__ float g_deg[NN];
__device__ float g_delta;

// ---------------------------------------------------------------------------
// deg[i] = sum_j A[i][j]   (warp per row)
// ---------------------------------------------------------------------------
__global__ void deg_kernel(const float* __restrict__ A) {
    int row  = blockIdx.x * (blockDim.x >> 5) + (threadIdx.x >> 5);
    int lane = threadIdx.x & 31;
    const float* r = A + (size_t)row * NN;
    float s = 0.f;
    for (int j = lane; j < NN; j += 32) s += r[j];
    #pragma unroll
    for (int o = 16; o; o >>= 1) s += __shfl_xor_sync(0xffffffffu, s, o);
    if (lane == 0) g_deg[row] = s;
}

// ---------------------------------------------------------------------------
// delta = mean(log(deg + 1))
// ---------------------------------------------------------------------------
__global__ void delta_kernel() {
    __shared__ float red[32];
    int tid = threadIdx.x;
    float s = 0.f;
    for (int i = tid; i < NN; i += blockDim.x) s += logf(g_deg[i] + 1.f);
    #pragma unroll
    for (int o = 16; o; o >>= 1) s += __shfl_xor_sync(0xffffffffu, s, o);
    if ((tid & 31) == 0) red[tid >> 5] = s;
    __syncthreads();
    if (tid < 32) {
        float v = (tid < (int)(blockDim.x >> 5)) ? red[tid] : 0.f;
        #pragma unroll
        for (int o = 16; o; o >>= 1) v += __shfl_xor_sync(0xffffffffu, v, o);
        if (tid == 0) g_delta = v / (float)NN;
    }
}

// ---------------------------------------------------------------------------
// Transpose X [b][c][n][p] -> g_xp [b*p][n][c]  (output-coalesced)
// ---------------------------------------------------------------------------
__global__ void transpose_kernel(const float* __restrict__ X) {
    int idx = blockIdx.x * blockDim.x + threadIdx.x;
    if (idx >= BB * PP * NN * CC) return;
    int ch = idx & (CC - 1);
    int j  = (idx >> 5) & (NN - 1);
    int bp = idx >> 16;                 // (5 bits c) + (11 bits n)
    int b = bp / PP, p = bp % PP;
    g_xp[idx] = X[(((size_t)b * CC + ch) * NN + j) * PP + p];
}

// ---------------------------------------------------------------------------
// Fused main kernel: per (bp, 128-node dest tile)
//   1) ACC[128][256] = A_tile @ F   (F generated on the fly in smem)
//      Feature column layout g*32+ch:  g0=S1 g1=S2 g2=S3 g3=S4
//                                      g4=SXP g5=SEP g6=SXN g7=SEN
//   2) In-place aggregator epilogue (softmin, softmax, m1, std, var, dist, d_std)
//   3) Scaler-folded Theta projection + bias + leaky relu, write [b,o,n,p]
// ---------------------------------------------------------------------------
__global__ __launch_bounds__(512, 1)
void pna_kernel(const float* __restrict__ A, const float* __restrict__ Theta,
                const float* __restrict__ Bias, float* __restrict__ out) {
    extern __shared__ float sm[];
    const int bp = blockIdx.y;
    const int i0 = blockIdx.x * TM;
    const int b  = bp / PP, p = bp % PP;
    const float* __restrict__ xp = g_xp + (size_t)bp * NN * CC;

    float* As = sm;                 // [KT][TM]      (stride 128, aligned float4 reads)
    float* Fs = sm + KT * TM;       // [KT][TN]

    const int tid = threadIdx.x;
    const int ty = tid >> 5;        // 0..15
    const int tx = tid & 31;        // 0..31

    float acc[8][8];
    #pragma unroll
    for (int r = 0; r < 8; r++)
        #pragma unroll
        for (int c2 = 0; c2 < 8; c2++) acc[r][c2] = 0.f;

    const int ati = tid >> 2;            // 0..127  dest row within tile
    const int akk = (tid & 3) << 3;      // 0,8,16,24

    for (int k0 = 0; k0 < NN; k0 += KT) {
        // ---- stage A tile (transposed into As[kk][ti]) ----
        {
            const float4* src = reinterpret_cast<const float4*>(
                A + (size_t)(i0 + ati) * NN + k0 + akk);
            float4 v0 = src[0], v1 = src[1];
            As[(akk + 0) * TM + ati] = v0.x;
            As[(akk + 1) * TM + ati] = v0.y;
            As[(akk + 2) * TM + ati] = v0.z;
            As[(akk + 3) * TM + ati] = v0.w;
            As[(akk + 4) * TM + ati] = v1.x;
            As[(akk + 5) * TM + ati] = v1.y;
            As[(akk + 6) * TM + ati] = v1.z;
            As[(akk + 7) * TM + ati] = v1.w;
        }
        // ---- generate F tile: 32 source nodes x 8 features x 32 channels ----
        #pragma unroll
        for (int it = 0; it < 2; it++) {
            int e  = tid + it * 512;         // 0..1023
            int kk = e >> 5, ch = e & 31;
            float x  = xp[(size_t)(k0 + kk) * CC + ch];
            float x2 = x * x;
            float ep = expf(x);
            float en = expf(-x);
            float* f = Fs + kk * TN + ch;
            f[0]   = x;         // S1
            f[32]  = x2;        // S2
            f[64]  = x2 * x;    // S3
            f[96]  = x2 * x2;   // S4
            f[128] = x * ep;    // SXP
            f[160] = ep;        // SEP
            f[192] = x * en;    // SXN
            f[224] = en;        // SEN
        }
        __syncthreads();
        // ---- 128x256x32 FMA tile ----
        #pragma unroll 4
        for (int kk = 0; kk < KT; kk++) {
            float4 a0 = *reinterpret_cast<const float4*>(As + kk * TM + ty * 8);
            float4 a1 = *reinterpret_cast<const float4*>(As + kk * TM + ty * 8 + 4);
            float4 b0 = *reinterpret_cast<const float4*>(Fs + kk * TN + tx * 8);
            float4 b1 = *reinterpret_cast<const float4*>(Fs + kk * TN + tx * 8 + 4);
            float av[8] = {a0.x, a0.y, a0.z, a0.w, a1.x, a1.y, a1.z, a1.w};
            float bv[8] = {b0.x, b0.y, b0.z, b0.w, b1.x, b1.y, b1.z, b1.w};
            #pragma unroll
            for (int r = 0; r < 8; r++)
                #pragma unroll
                for (int c2 = 0; c2 < 8; c2++)
                    acc[r][c2] = fmaf(av[r], bv[c2], acc[r][c2]);
        }
        __syncthreads();
    }

    // ---- spill accumulators to smem: ACC[128][256] (overwrites As/Fs) ----
    float* ACC = sm;
    #pragma unroll
    for (int r = 0; r < 8; r++) {
        float4* d = reinterpret_cast<float4*>(&ACC[(ty * 8 + r) * TN + tx * 8]);
        d[0] = make_float4(acc[r][0], acc[r][1], acc[r][2], acc[r][3]);
        d[1] = make_float4(acc[r][4], acc[r][5], acc[r][6], acc[r][7]);
    }
    __syncthreads();

    // ---- phase A: aggregator math, in place (each thread owns (i,ch) slots) ----
    for (int e = tid; e < TM * CC; e += 512) {
        int i  = e >> 5;
        int ch = e & 31;
        float* row = &ACC[i * TN];
        float S1  = row[ch],       S2  = row[32 + ch];
        float S3  = row[64 + ch],  S4  = row[96 + ch];
        float SXP = row[128 + ch], SEP = row[160 + ch];
        float SXN = row[192 + ch], SEN = row[224 + ch];

        float x    = xp[(size_t)(i0 + i) * CC + ch];
        float dg   = g_deg[i0 + i];
        float dinv = 1.f / fmaxf(dg, EPSV);
        float m1 = S1 * dinv, m2 = S2 * dinv, m3 = S3 * dinv, m4 = S4 * dinv;
        float smax = SXP / (SEP + EPSV);
        float smin = SXN / (SEN + EPSV);
        float var  = fmaxf(m2 - m1 * m1, 0.f);
        float stdv = sqrtf(var + EPSV);
        float x2 = x * x, x3 = x2 * x, x4 = x2 * x2;
        float dist = x2 - 2.f * x * m1 + m2;
        float ed2  = x4 - 4.f * x3 * m1 + 6.f * x2 * m2 - 4.f * x * m3 + m4;
        float dstd = sqrtf(fmaxf(ed2 - dist * dist, 0.f) + EPSV);

        // feature order: softmin, softmax, mean, std, var, dist, d_std
        row[ch]        = smin;
        row[32  + ch]  = smax;
        row[64  + ch]  = m1;
        row[96  + ch]  = stdv;
        row[128 + ch]  = var;
        row[160 + ch]  = dist;
        row[192 + ch]  = dstd;
    }
    __syncthreads();

    // ---- phase B: scaler-folded Theta projection ----
    // out[o] = Bias[o] + sum_f feats[f] * (Th[f,o] + s*Th[224+f,o] + inv*Th[448+f,o])
    const float delta = g_delta;
    const int o = tx;
    for (int r = 0; r < 8; r++) {
        int i = ty * 8 + r;
        float dg  = g_deg[i0 + i];
        float s   = logf(dg + 1.f) / delta;
        float inv = 1.f / fmaxf(s, EPSV);
        const float* row = &ACC[i * TN];
        float accO = Bias[o];
        #pragma unroll 8
        for (int f = 0; f < 224; f++) {
            float fv = row[f];                              // smem broadcast
            float t  = Theta[f * OUTC + o]
                     + s   * Theta[(224 + f) * OUTC + o]
                     + inv * Theta[(448 + f) * OUTC + o];
            accO = fmaf(fv, t, accO);
        }
        accO = accO > 0.f ? accO : NEG_SLOPE * accO;
        out[(((size_t)b * OUTC + o) * NN + (i0 + i)) * PP + p] = accO;
    }
}

// ---------------------------------------------------------------------------
extern "C" void kernel_launch(void* const* d_in, const int* in_sizes, int n_in,
                              void* d_out, int out_size) {
    const float* X     = (const float*)d_in[0];   // [4,32,2048,12]
    const float* A     = (const float*)d_in[1];   // [2048,2048]
    const float* Theta = (const float*)d_in[2];   // [672,32]
    const float* Bias  = (const float*)d_in[3];   // [32]
    float* out = (float*)d_out;                   // [4,32,2048,12]

    const int smem = TM * TN * (int)sizeof(float);   // 131072 B
    cudaFuncSetAttribute(pna_kernel, cudaFuncAttributeMaxDynamicSharedMemorySize, smem);

    deg_kernel<<<NN / 8, 256>>>(A);
    delta_kernel<<<1, 1024>>>();
    transpose_kernel<<<(BB * PP * NN * CC + 255) / 256, 256>>>(X);

    dim3 grid(NN / TM, BB * PP);
    pna_kernel<<<grid, 512, smem>>>(A, Theta, Bias, out);
}